// round 3
// baseline (speedup 1.0000x reference)
#include <cuda_runtime.h>
#include <math.h>

#define Bn 65536
#define Dt 768
#define Dim 2048
#define Dd 300

// small precomputed scratch (allocation-free: __device__ globals)
__device__ float g_WkT[3 * Dd * Dd];
__device__ float g_A[3 * Dd * Dd];
__device__ float g_w[3 * Dd];
__device__ float g_c[3];

// transpose a [300,300] matrix: out[d*300+j] = in[j*300+d]
__global__ void k_transpose(const float* __restrict__ in, float* __restrict__ out) {
    int idx = blockIdx.x * 256 + threadIdx.x;
    if (idx < Dd * Dd) {
        int j = idx / Dd, d = idx % Dd;
        out[d * Dd + j] = in[idx];
    }
}

// w[i] = sum_d Wq[i,d]*bk[d] + Wk[i,d]*bq[d] ;  c = bq.bk
__global__ void k_wc(const float* __restrict__ Wq, const float* __restrict__ bq,
                     const float* __restrict__ Wk, const float* __restrict__ bk,
                     float* __restrict__ w_out, float* __restrict__ c_out) {
    int i = threadIdx.x;
    __shared__ float sred[320];
    if (i < Dd) {
        float s = 0.f;
        for (int d = 0; d < Dd; d++)
            s += Wq[i * Dd + d] * bk[d] + Wk[i * Dd + d] * bq[d];
        w_out[i] = s;
    }
    sred[i] = (i < Dd) ? bq[i] * bk[i] : 0.f;
    __syncthreads();
    for (int s = 256; s > 0; s >>= 1) {
        if (i < s && i + s < 320) sred[i] += sred[i + s];
        __syncthreads();
    }
    if (i == 0) *c_out = sred[0];
}

// out[M,300] = X[M,K] @ W[K,300] (+ bias). CTA: 32 rows x 300 cols, 320 threads.
template <int K, bool GUARD>
__global__ void __launch_bounds__(320, 2)
k_gemm(const float* __restrict__ X, const float* __restrict__ W,
       const float* __restrict__ bias, float* __restrict__ out, int M) {
    constexpr int TM = 32, KB = 32;
    __shared__ float xs[TM][KB];
    const int tid = threadIdx.x;
    const int j = tid;                 // output column
    const int row0 = blockIdx.x * TM;
    float acc[TM];
#pragma unroll
    for (int r = 0; r < TM; r++) acc[r] = 0.f;
    const int lr = tid >> 3, lk = (tid & 7) << 2;  // loader mapping (256 float4s)

    for (int k0 = 0; k0 < K; k0 += KB) {
        __syncthreads();
        if (tid < 256) {
            float4 v = make_float4(0.f, 0.f, 0.f, 0.f);
            int row = row0 + lr;
            bool okr = (!GUARD) || (row < M);
            bool okk = (K % KB == 0) || (k0 + lk < K);
            if (okr && okk)
                v = *reinterpret_cast<const float4*>(&X[(size_t)row * K + k0 + lk]);
            *reinterpret_cast<float4*>(&xs[lr][lk]) = v;
        }
        __syncthreads();
        if (j < Dd) {
#pragma unroll
            for (int kq = 0; kq < KB; kq += 4) {
                const float* wp = W + (size_t)(k0 + kq) * Dd + j;
                float w0 = 0.f, w1 = 0.f, w2 = 0.f, w3 = 0.f;
                if ((K % KB == 0) || (k0 + kq + 0 < K)) w0 = wp[0];
                if ((K % KB == 0) || (k0 + kq + 1 < K)) w1 = wp[Dd];
                if ((K % KB == 0) || (k0 + kq + 2 < K)) w2 = wp[2 * Dd];
                if ((K % KB == 0) || (k0 + kq + 3 < K)) w3 = wp[3 * Dd];
#pragma unroll
                for (int r = 0; r < TM; r++) {
                    float4 x4 = *reinterpret_cast<const float4*>(&xs[r][kq]);
                    acc[r] = fmaf(x4.x, w0, acc[r]);
                    acc[r] = fmaf(x4.y, w1, acc[r]);
                    acc[r] = fmaf(x4.z, w2, acc[r]);
                    acc[r] = fmaf(x4.w, w3, acc[r]);
                }
            }
        }
    }
    if (j < Dd) {
        float b = bias ? bias[j] : 0.f;
#pragma unroll
        for (int r = 0; r < TM; r++) {
            int row = row0 + r;
            if ((!GUARD) || (row < M))
                out[(size_t)row * Dd + j] = acc[r] + b;
        }
    }
}

// per-row quadratic forms -> sigmoid -> softmax weights -> scale out1/out2 in place
__global__ void __launch_bounds__(320, 2)
k_scalar(float* __restrict__ d_out) {
    constexpr int TM = 32;
    __shared__ float Psm[TM][304];
    __shared__ float red[10][TM];
    __shared__ float alphas[3][TM];
    __shared__ float fac[2][TM];
    const int tid = threadIdx.x;
    const int j = tid;
    const int lane = tid & 31, wrp = tid >> 5;
    const int row0 = blockIdx.x * TM;
    float* out0 = d_out;
    float* out1 = d_out + (size_t)Bn * Dd;
    float* out2 = d_out + 2 * (size_t)Bn * Dd;
    const float* srcs[3] = {out0, out1, out2};

    for (int z = 0; z < 3; z++) {
        __syncthreads();  // protect Psm / red reuse
        const float* src = srcs[z];
        for (int flat = tid; flat < TM * Dd; flat += 320) {
            int r = flat / Dd, c = flat % Dd;
            Psm[r][c] = src[(size_t)(row0 + r) * Dd + c];
        }
        __syncthreads();

        float acc[TM];
#pragma unroll
        for (int r = 0; r < TM; r++) acc[r] = 0.f;
        const float* A = g_A + z * Dd * Dd;
        if (j < Dd) {
            for (int i4 = 0; i4 < Dd; i4 += 4) {
                float a0 = A[(i4 + 0) * Dd + j];
                float a1 = A[(i4 + 1) * Dd + j];
                float a2 = A[(i4 + 2) * Dd + j];
                float a3 = A[(i4 + 3) * Dd + j];
#pragma unroll
                for (int r = 0; r < TM; r++) {
                    float4 p4 = *reinterpret_cast<const float4*>(&Psm[r][i4]);
                    acc[r] = fmaf(p4.x, a0, acc[r]);
                    acc[r] = fmaf(p4.y, a1, acc[r]);
                    acc[r] = fmaf(p4.z, a2, acc[r]);
                    acc[r] = fmaf(p4.w, a3, acc[r]);
                }
            }
        }
        float wj = (j < Dd) ? g_w[z * Dd + j] : 0.f;
#pragma unroll
        for (int r = 0; r < TM; r++) {
            float v = (j < Dd) ? (acc[r] + wj) * Psm[r][j] : 0.f;
#pragma unroll
            for (int off = 16; off > 0; off >>= 1)
                v += __shfl_xor_sync(0xffffffffu, v, off);
            if (lane == r) red[wrp][r] = v;   // all lanes hold warp sum after butterfly
        }
        __syncthreads();
        if (tid < TM) {
            float s = 0.f;
#pragma unroll
            for (int w = 0; w < 10; w++) s += red[w][tid];
            alphas[z][tid] = s + g_c[z];
        }
    }
    __syncthreads();
    if (tid < TM) {
        const float inv = 0.05773502691896258f;  // 1/sqrt(300)
        float zT = 1.f / (1.f + expf(-alphas[0][tid] * inv));
        float zI = 1.f / (1.f + expf(-alphas[1][tid] * inv));
        float zC = 1.f / (1.f + expf(-alphas[2][tid] * inv));
        // softmax over [zI*zT, zC*zT]: a1 = sigmoid(zT*(zI - zC))
        float a1 = 1.f / (1.f + expf(zT * (zC - zI)));
        fac[0][tid] = a1;
        fac[1][tid] = 1.f - a1;
    }
    __syncthreads();
    for (int flat = tid; flat < TM * Dd; flat += 320) {
        int r = flat / Dd, c = flat % Dd;
        size_t idx = (size_t)(row0 + r) * Dd + c;
        out1[idx] *= fac[0][r];
        out2[idx] *= fac[1][r];
    }
}

extern "C" void kernel_launch(void* const* d_in, const int* in_sizes, int n_in,
                              void* d_out, int out_size) {
    const float* T   = (const float*)d_in[0];
    const float* IM  = (const float*)d_in[1];
    const float* CD  = (const float*)d_in[2];
    const float* Wt  = (const float*)d_in[3];
    const float* bt  = (const float*)d_in[4];
    const float* Wim = (const float*)d_in[5];
    const float* bim = (const float*)d_in[6];
    const float* Wq[3] = {(const float*)d_in[7],  (const float*)d_in[11], (const float*)d_in[15]};
    const float* bq[3] = {(const float*)d_in[8],  (const float*)d_in[12], (const float*)d_in[16]};
    const float* Wk[3] = {(const float*)d_in[9],  (const float*)d_in[13], (const float*)d_in[17]};
    const float* bk[3] = {(const float*)d_in[10], (const float*)d_in[14], (const float*)d_in[18]};

    float *gWkT, *gA, *gw, *gc;
    cudaGetSymbolAddress((void**)&gWkT, g_WkT);
    cudaGetSymbolAddress((void**)&gA,   g_A);
    cudaGetSymbolAddress((void**)&gw,   g_w);
    cudaGetSymbolAddress((void**)&gc,   g_c);

    float* out  = (float*)d_out;
    float* out0 = out;
    float* out1 = out + (size_t)Bn * Dd;
    float* out2 = out + 2 * (size_t)Bn * Dd;

    const int tgrid = (Dd * Dd + 255) / 256;
    for (int z = 0; z < 3; z++) {
        k_transpose<<<tgrid, 256>>>(Wk[z], gWkT + z * Dd * Dd);
        k_wc<<<1, 320>>>(Wq[z], bq[z], Wk[z], bk[z], gw + z * Dd, gc + z);
    }
    // A_z = Wq_z @ Wk_z^T   (M=300, K=300)
    for (int z = 0; z < 3; z++)
        k_gemm<Dd, true><<<(Dd + 31) / 32, 320>>>(Wq[z], gWkT + z * Dd * Dd,
                                                  nullptr, gA + z * Dd * Dd, Dd);
    // projections (unscaled IM/CD written straight into output regions)
    k_gemm<Dt,  false><<<Bn / 32, 320>>>(T,  Wt,  bt,  out0, Bn);
    k_gemm<Dim, false><<<Bn / 32, 320>>>(IM, Wim, bim, out1, Bn);
    k_gemm<Dt,  false><<<Bn / 32, 320>>>(CD, Wt,  bt,  out2, Bn);
    // quadratic forms + sigmoid/softmax + in-place scaling
    k_scalar<<<Bn / 32, 320>>>(out);
}

// round 6
// speedup vs baseline: 4.1377x; 4.1377x over previous
#include <cuda_runtime.h>
#include <math.h>
#include <stdint.h>

#define Bn 65536
#define Dt 768
#define Dim 2048
#define Dd 300
#define NP 320                    // padded N
#define STRIDE 36                 // smem row stride (floats)
#define AF 2304                   // A stage floats (64*36)
#define BF 11520                  // B stage floats (320*36)
#define STG (AF + BF)             // 13824 floats per stage
#define STGB (STG * 4)            // 55296 bytes
#define SMEM_SZ (2 * STGB)
#define BCHB (NP * STRIDE * 4)    // B image bytes per chunk = 46080
#define BF4 (BCHB / 16)           // 2880 float4 per chunk

__device__ float g_WkT[3 * Dd * Dd];
__device__ float g_A[3 * Dd * Dd];
__device__ float g_w[3 * Dd];
__device__ float g_c[3];
__device__ float g_alpha[3 * Bn];
__device__ float g_fac[2 * Bn];
__device__ float g_imgWt[24 * NP * STRIDE];
__device__ float g_imgWim[64 * NP * STRIDE];
__device__ float g_imgA[3 * 10 * NP * STRIDE];

struct WPtrs { const float *wq[3], *bq[3], *wk[3], *bk[3]; };

__device__ __forceinline__ uint32_t smem_u32(const void* p) {
    uint32_t a;
    asm("{ .reg .u64 t; cvta.to.shared.u64 t, %1; cvt.u32.u64 %0, t; }" : "=r"(a) : "l"(p));
    return a;
}
__device__ __forceinline__ float tf32r(float x) {
    uint32_t r; asm("cvt.rna.tf32.f32 %0, %1;" : "=r"(r) : "f"(x));
    return __uint_as_float(r);
}
__device__ __forceinline__ void cp16(uint32_t dst, const void* src) {
    asm volatile("cp.async.cg.shared.global [%0], [%1], 16;" :: "r"(dst), "l"(src));
}
__device__ __forceinline__ void cp_commit() { asm volatile("cp.async.commit_group;" ::: "memory"); }
__device__ __forceinline__ void cp_wait0() { asm volatile("cp.async.wait_group 0;" ::: "memory"); }

#define MMA8(d, a, b) \
    asm volatile("mma.sync.aligned.m16n8k8.row.col.f32.tf32.tf32.f32 " \
        "{%0,%1,%2,%3}, {%4,%5,%6,%7}, {%8,%9}, {%0,%1,%2,%3};" \
        : "+f"(d[0]), "+f"(d[1]), "+f"(d[2]), "+f"(d[3]) \
        : "r"(a[0]), "r"(a[1]), "r"(a[2]), "r"(a[3]), "r"(b[0]), "r"(b[1]))

// ---- main GEMM: C[64x320] += X[64xK] @ W[Kx320]; MODE0: out=C+bias; MODE1: alpha=rowdot(C+w, X)
template <int KACT, int NC, int MODE>
__global__ void __launch_bounds__(512, 1)
k_mma(const float* __restrict__ X, const float* __restrict__ img,
      const float* __restrict__ bias, float* __restrict__ out, float* __restrict__ alpha) {
    extern __shared__ float sm[];
    const uint32_t sbase = smem_u32(sm);
    const int tid = threadIdx.x, lane = tid & 31, wid = tid >> 5;
    const int wm = wid & 1, wn = wid >> 1;
    const int g = lane >> 2, tg = lane & 3;
    const int row0 = blockIdx.x * 64;
    const int lr = tid >> 3, lf = tid & 7;   // A loader: row, float4-pos

    float acc[2][5][4];
#pragma unroll
    for (int mi = 0; mi < 2; mi++)
#pragma unroll
        for (int ni = 0; ni < 5; ni++)
#pragma unroll
            for (int q = 0; q < 4; q++) acc[mi][ni][q] = 0.f;

    // ---- A loader (gmem -> regs, tf32-rounded)
    auto loadA = [&](int c, float4& v) {
        int k0 = c * 32 + lf * 4;
        const float* xr = X + (size_t)(row0 + lr) * KACT + k0;
        if (KACT % 32 == 0) {
            v = *reinterpret_cast<const float4*>(xr);
        } else if (k0 + 3 < KACT) {
            v = *reinterpret_cast<const float4*>(xr);
        } else {
            v.x = (k0 + 0 < KACT) ? xr[0] : 0.f;
            v.y = (k0 + 1 < KACT) ? xr[1] : 0.f;
            v.z = (k0 + 2 < KACT) ? xr[2] : 0.f;
            v.w = (k0 + 3 < KACT) ? xr[3] : 0.f;
        }
        v.x = tf32r(v.x); v.y = tf32r(v.y); v.z = tf32r(v.z); v.w = tf32r(v.w);
    };
    auto storeA = [&](int buf, const float4& v) {
        *reinterpret_cast<float4*>(&sm[buf * STG + lr * STRIDE + lf * 4]) = v;
    };
    auto issueB = [&](int c, int buf) {
        const char* src = reinterpret_cast<const char*>(img) + (size_t)c * BCHB;
        uint32_t d = sbase + buf * STGB + AF * 4;
        for (int i = tid; i < BF4; i += 512) cp16(d + i * 16, src + i * 16);
        cp_commit();
    };

    // prologue
    float4 av;
    loadA(0, av);
    storeA(0, av);
    issueB(0, 0);

    for (int c = 0; c < NC; c++) {
        const int buf = c & 1;
        if (c + 1 < NC) loadA(c + 1, av);
        cp_wait0();
        __syncthreads();
        if (c + 1 < NC) { storeA(buf ^ 1, av); issueB(c + 1, buf ^ 1); }

        const float* As = sm + buf * STG;
        const float* Bs = sm + buf * STG + AF;
#pragma unroll
        for (int s = 0; s < 4; s++) {
            const int k0 = s * 8 + tg;            // fragment K base for this thread
            uint32_t a[2][4], b[5][2];
#pragma unroll
            for (int mi = 0; mi < 2; mi++) {
                const float* ar = &As[(wm*32 + mi*16 + g) * STRIDE];
                // PTX m16n8k8 A map: a0=(g,tg) a1=(g+8,tg) a2=(g,tg+4) a3=(g+8,tg+4)
                a[mi][0] = __float_as_uint(ar[k0]);
                a[mi][1] = __float_as_uint(ar[8 * STRIDE + k0]);
                a[mi][2] = __float_as_uint(ar[k0 + 4]);
                a[mi][3] = __float_as_uint(ar[8 * STRIDE + k0 + 4]);
            }
#pragma unroll
            for (int ni = 0; ni < 5; ni++) {
                const float* br = &Bs[(wn*40 + ni*8 + g) * STRIDE];
                // PTX B map: b0=(k=tg, n=g) b1=(k=tg+4, n=g)
                b[ni][0] = __float_as_uint(br[k0]);
                b[ni][1] = __float_as_uint(br[k0 + 4]);
            }
#pragma unroll
            for (int mi = 0; mi < 2; mi++)
#pragma unroll
                for (int ni = 0; ni < 5; ni++) MMA8(acc[mi][ni], a[mi], b[ni]);
        }
    }

    if (MODE == 0) {
#pragma unroll
        for (int mi = 0; mi < 2; mi++) {
            const int r1 = row0 + wm*32 + mi*16 + g, r2 = r1 + 8;
#pragma unroll
            for (int ni = 0; ni < 5; ni++) {
                const int col = wn*40 + ni*8 + 2*tg;
                if (col < Dd) {
                    float2 bb = *reinterpret_cast<const float2*>(&bias[col]);
                    float2 o1 = make_float2(acc[mi][ni][0] + bb.x, acc[mi][ni][1] + bb.y);
                    float2 o2 = make_float2(acc[mi][ni][2] + bb.x, acc[mi][ni][3] + bb.y);
                    *reinterpret_cast<float2*>(&out[(size_t)r1 * Dd + col]) = o1;
                    *reinterpret_cast<float2*>(&out[(size_t)r2 * Dd + col]) = o2;
                }
            }
        }
    } else {
        float pr[4] = {0.f, 0.f, 0.f, 0.f};   // [mi*2 + (0: row g, 1: row g+8)]
#pragma unroll
        for (int mi = 0; mi < 2; mi++) {
            const int r1 = row0 + wm*32 + mi*16 + g, r2 = r1 + 8;
#pragma unroll
            for (int ni = 0; ni < 5; ni++) {
                const int col = wn*40 + ni*8 + 2*tg;
                if (col < Dd) {
                    float2 ww = *reinterpret_cast<const float2*>(&bias[col]);  // bias = g_w slice
                    float2 p1 = *reinterpret_cast<const float2*>(&X[(size_t)r1 * Dd + col]);
                    float2 p2 = *reinterpret_cast<const float2*>(&X[(size_t)r2 * Dd + col]);
                    pr[mi*2+0] += (acc[mi][ni][0] + ww.x) * p1.x + (acc[mi][ni][1] + ww.y) * p1.y;
                    pr[mi*2+1] += (acc[mi][ni][2] + ww.x) * p2.x + (acc[mi][ni][3] + ww.y) * p2.y;
                }
            }
        }
#pragma unroll
        for (int j = 0; j < 4; j++) {
            pr[j] += __shfl_xor_sync(0xffffffffu, pr[j], 1);
            pr[j] += __shfl_xor_sync(0xffffffffu, pr[j], 2);
        }
        __syncthreads();                       // stage smem free for reduction
        float* red = sm;                       // [8][64]
        if (tg == 0) {
#pragma unroll
            for (int mi = 0; mi < 2; mi++) {
                red[wn * 64 + wm*32 + mi*16 + g]     = pr[mi*2+0];
                red[wn * 64 + wm*32 + mi*16 + g + 8] = pr[mi*2+1];
            }
        }
        __syncthreads();
        if (tid < 64) {
            float s = 0.f;
#pragma unroll
            for (int w = 0; w < 8; w++) s += red[w * 64 + tid];
            alpha[row0 + tid] = s;
        }
    }
}

// ---- prep kernels ----
__global__ void k_transpose3(const float* __restrict__ k0, const float* __restrict__ k1,
                             const float* __restrict__ k2) {
    int idx = blockIdx.x * 256 + threadIdx.x;
    if (idx >= 3 * Dd * Dd) return;
    int z = idx / (Dd * Dd), r = idx - z * (Dd * Dd);
    int j = r / Dd, d = r - j * Dd;
    const float* Wk = (z == 0) ? k0 : ((z == 1) ? k1 : k2);
    g_WkT[z * Dd * Dd + d * Dd + j] = Wk[j * Dd + d];
}

__global__ void k_wc(WPtrs p) {
    int i = blockIdx.x, z = blockIdx.y, t = threadIdx.x;
    float s = 0.f;
    if (i < Dd) {
        for (int d = t; d < Dd; d += 128)
            s += p.wq[z][i * Dd + d] * p.bk[z][d] + p.wk[z][i * Dd + d] * p.bq[z][d];
    } else {
        for (int d = t; d < Dd; d += 128) s += p.bq[z][d] * p.bk[z][d];
    }
#pragma unroll
    for (int o = 16; o > 0; o >>= 1) s += __shfl_xor_sync(0xffffffffu, s, o);
    __shared__ float smr[4];
    if ((t & 31) == 0) smr[t >> 5] = s;
    __syncthreads();
    if (t == 0) {
        float tot = smr[0] + smr[1] + smr[2] + smr[3];
        if (i < Dd) g_w[z * Dd + i] = tot; else g_c[z] = tot;
    }
}

__global__ void __launch_bounds__(320, 2)
k_gemmA(WPtrs p) {
    constexpr int TM = 32, KB = 32, K = Dd, M = Dd;
    const int z = blockIdx.y;
    const float* X = p.wq[z];
    const float* W = g_WkT + z * Dd * Dd;
    float* out = g_A + z * Dd * Dd;
    __shared__ float xs[TM][KB];
    const int tid = threadIdx.x, j = tid, row0 = blockIdx.x * TM;
    float acc[TM];
#pragma unroll
    for (int r = 0; r < TM; r++) acc[r] = 0.f;
    const int lr = tid >> 3, lk = (tid & 7) << 2;
    for (int k0 = 0; k0 < K; k0 += KB) {
        __syncthreads();
        if (tid < 256) {
            float4 v = make_float4(0.f, 0.f, 0.f, 0.f);
            int row = row0 + lr;
            if (row < M && k0 + lk < K)
                v = *reinterpret_cast<const float4*>(&X[(size_t)row * K + k0 + lk]);
            *reinterpret_cast<float4*>(&xs[lr][lk]) = v;
        }
        __syncthreads();
        if (j < Dd) {
#pragma unroll
            for (int kq = 0; kq < KB; kq += 4) {
                const float* wp = W + (size_t)(k0 + kq) * Dd + j;
                float w0 = (k0+kq+0 < K) ? wp[0] : 0.f;
                float w1 = (k0+kq+1 < K) ? wp[Dd] : 0.f;
                float w2 = (k0+kq+2 < K) ? wp[2*Dd] : 0.f;
                float w3 = (k0+kq+3 < K) ? wp[3*Dd] : 0.f;
#pragma unroll
                for (int r = 0; r < TM; r++) {
                    float4 x4 = *reinterpret_cast<const float4*>(&xs[r][kq]);
                    acc[r] = fmaf(x4.x, w0, acc[r]); acc[r] = fmaf(x4.y, w1, acc[r]);
                    acc[r] = fmaf(x4.z, w2, acc[r]); acc[r] = fmaf(x4.w, w3, acc[r]);
                }
            }
        }
    }
    if (j < Dd)
#pragma unroll
        for (int r = 0; r < TM; r++)
            if (row0 + r < M) out[(size_t)(row0 + r) * Dd + j] = acc[r];
}

// B image: [chunk][n(320) stride 36][k(32)], element (k,n) = tf32r(W[k, n]), zero-padded
__global__ void k_bimg(const float* __restrict__ W, int kact, int nch, float* __restrict__ dst) {
    int i = blockIdx.x * 256 + threadIdx.x;
    if (i >= nch * NP * 32) return;
    int chunk = i / (NP * 32), r = i - chunk * (NP * 32);
    int n = r >> 5, k = r & 31;
    int kg = chunk * 32 + k;
    float v = (n < Dd && kg < kact) ? tf32r(W[(size_t)kg * Dd + n]) : 0.f;
    dst[(size_t)chunk * (NP * STRIDE) + n * STRIDE + k] = v;
}

__global__ void k_fac() {
    int i = blockIdx.x * 256 + threadIdx.x;
    if (i >= Bn) return;
    const float inv = 0.057735026918962576f;  // 1/sqrt(300)
    float zT = 1.f / (1.f + expf(-(g_alpha[i] + g_c[0]) * inv));
    float zI = 1.f / (1.f + expf(-(g_alpha[Bn + i] + g_c[1]) * inv));
    float zC = 1.f / (1.f + expf(-(g_alpha[2*Bn + i] + g_c[2]) * inv));
    float f = 1.f / (1.f + expf(zT * (zC - zI)));
    g_fac[i] = f;
    g_fac[Bn + i] = 1.f - f;
}

__global__ void k_scale(float4* __restrict__ o1, float4* __restrict__ o2) {
    int i = blockIdx.x * 256 + threadIdx.x;
    if (i >= Bn * 75) return;
    int r = i / 75;
    float f0 = g_fac[r], f1 = g_fac[Bn + r];
    float4 v = o1[i];
    v.x *= f0; v.y *= f0; v.z *= f0; v.w *= f0; o1[i] = v;
    float4 u = o2[i];
    u.x *= f1; u.y *= f1; u.z *= f1; u.w *= f1; o2[i] = u;
}

extern "C" void kernel_launch(void* const* d_in, const int* in_sizes, int n_in,
                              void* d_out, int out_size) {
    const float* T   = (const float*)d_in[0];
    const float* IM  = (const float*)d_in[1];
    const float* CD  = (const float*)d_in[2];
    const float* Wt  = (const float*)d_in[3];
    const float* bt  = (const float*)d_in[4];
    const float* Wim = (const float*)d_in[5];
    const float* bim = (const float*)d_in[6];
    WPtrs p;
    for (int z = 0; z < 3; z++) {
        p.wq[z] = (const float*)d_in[7 + 4*z];
        p.bq[z] = (const float*)d_in[8 + 4*z];
        p.wk[z] = (const float*)d_in[9 + 4*z];
        p.bk[z] = (const float*)d_in[10 + 4*z];
    }

    float *gA, *gw, *gAl, *gIWt, *gIWim, *gIA;
    cudaGetSymbolAddress((void**)&gA, g_A);
    cudaGetSymbolAddress((void**)&gw, g_w);
    cudaGetSymbolAddress((void**)&gAl, g_alpha);
    cudaGetSymbolAddress((void**)&gIWt, g_imgWt);
    cudaGetSymbolAddress((void**)&gIWim, g_imgWim);
    cudaGetSymbolAddress((void**)&gIA, g_imgA);

    cudaFuncSetAttribute(k_mma<Dt, 24, 0>,  cudaFuncAttributeMaxDynamicSharedMemorySize, SMEM_SZ);
    cudaFuncSetAttribute(k_mma<Dim, 64, 0>, cudaFuncAttributeMaxDynamicSharedMemorySize, SMEM_SZ);
    cudaFuncSetAttribute(k_mma<Dd, 10, 1>,  cudaFuncAttributeMaxDynamicSharedMemorySize, SMEM_SZ);

    float* out  = (float*)d_out;
    float* out0 = out;
    float* out1 = out + (size_t)Bn * Dd;
    float* out2 = out + 2 * (size_t)Bn * Dd;

    // prep
    k_transpose3<<<(3*Dd*Dd + 255)/256, 256>>>(p.wk[0], p.wk[1], p.wk[2]);
    k_wc<<<dim3(Dd + 1, 3), 128>>>(p);
    k_gemmA<<<dim3((Dd + 31)/32, 3), 320>>>(p);
    k_bimg<<<(24*NP*32 + 255)/256, 256>>>(Wt,  Dt,  24, gIWt);
    k_bimg<<<(64*NP*32 + 255)/256, 256>>>(Wim, Dim, 64, gIWim);
    for (int z = 0; z < 3; z++)
        k_bimg<<<(10*NP*32 + 255)/256, 256>>>(gA + z*Dd*Dd, Dd, 10, gIA + (size_t)z*10*NP*STRIDE);

    // projections (mma.sync tf32)
    k_mma<Dt,  24, 0><<<Bn/64, 512, SMEM_SZ>>>(T,  gIWt,  bt,  out0, nullptr);
    k_mma<Dim, 64, 0><<<Bn/64, 512, SMEM_SZ>>>(IM, gIWim, bim, out1, nullptr);
    k_mma<Dt,  24, 0><<<Bn/64, 512, SMEM_SZ>>>(CD, gIWt,  bt,  out2, nullptr);

    // quadratic forms: alpha_z = rowdot(P@A_z + w_z, P)
    for (int z = 0; z < 3; z++) {
        const float* src = (z == 0) ? out0 : ((z == 1) ? out1 : out2);
        k_mma<Dd, 10, 1><<<Bn/64, 512, SMEM_SZ>>>(
            src, gIA + (size_t)z*10*NP*STRIDE, gw + z*Dd, nullptr, gAl + (size_t)z*Bn);
    }

    k_fac<<<(Bn + 255)/256, 256>>>();
    k_scale<<<(Bn*75 + 255)/256, 256>>>((float4*)out1, (float4*)out2);
}

// round 9
// speedup vs baseline: 4.5925x; 1.1099x over previous
#include <cuda_runtime.h>
#include <math.h>
#include <stdint.h>

#define Bn 65536
#define Dt 768
#define Dim 2048
#define Dd 300
#define NP 320
#define ASTR 36                    // A stage row stride (floats)
#define ABYTES 18432               // 128*36*4
#define AWORDS 4608
#define BCHB 46080                 // B chunk bytes (320*36*4)
#define STAGEB (ABYTES + BCHB)     // 64512 bytes
#define STAGEF (STAGEB / 4)
#define SMEM_SZ (2 * STAGEB)

__device__ float g_WkT[3 * Dd * Dd];
__device__ float g_A[3 * Dd * Dd];
__device__ float g_w[3 * Dd];
__device__ float g_c[3];
__device__ float g_alpha[3 * Bn];
__device__ float g_fac[2 * Bn];
__device__ float g_imgWt[24 * NP * ASTR];
__device__ float g_imgWim[64 * NP * ASTR];
__device__ float g_imgA[3 * 10 * NP * ASTR];

struct WPtrs { const float *wq[3], *bq[3], *wk[3], *bk[3]; };

__device__ __forceinline__ uint32_t smem_u32(const void* p) {
    uint32_t a;
    asm("{ .reg .u64 t; cvta.to.shared.u64 t, %1; cvt.u32.u64 %0, t; }" : "=r"(a) : "l"(p));
    return a;
}
__device__ __forceinline__ float tf32r(float x) {
    uint32_t r; asm("cvt.rna.tf32.f32 %0, %1;" : "=r"(r) : "f"(x));
    return __uint_as_float(r);
}
__device__ __forceinline__ void cp16z(uint32_t dst, const void* src, uint32_t zf) {
    asm volatile("cp.async.cg.shared.global [%0], [%1], 16, %2;" :: "r"(dst), "l"(src), "r"(zf));
}
__device__ __forceinline__ void cp_commit() { asm volatile("cp.async.commit_group;" ::: "memory"); }
__device__ __forceinline__ void cp_wait0() { asm volatile("cp.async.wait_group 0;" ::: "memory"); }
__device__ __forceinline__ void cp_wait1() { asm volatile("cp.async.wait_group 1;" ::: "memory"); }

#define MMA8(d, a, b0, b1) \
    asm volatile("mma.sync.aligned.m16n8k8.row.col.f32.tf32.tf32.f32 " \
        "{%0,%1,%2,%3}, {%4,%5,%6,%7}, {%8,%9}, {%0,%1,%2,%3};" \
        : "+f"(d[0]), "+f"(d[1]), "+f"(d[2]), "+f"(d[3]) \
        : "r"(a[0]), "r"(a[1]), "r"(a[2]), "r"(a[3]), "r"(b0), "r"(b1))

// C[128x320] = X[128xK] @ W[Kx320]; MODE0: out=C+bias; MODE1: alpha=rowdot(C+w, X)
template <int KACT, int NC, int MODE>
__global__ void __launch_bounds__(512, 1)
k_mma(const float* __restrict__ X, const float* __restrict__ img,
      const float* __restrict__ bias, float* __restrict__ out, float* __restrict__ alpha) {
    extern __shared__ float sm[];
    const uint32_t sbase = smem_u32(sm);
    const int tid = threadIdx.x, lane = tid & 31, wid = tid >> 5;
    const int wm = wid & 1, wn = wid >> 1;        // 2 row-groups x 8 col-groups
    const int g = lane >> 2, tg = lane & 3;
    const int row0 = blockIdx.x * 128;

    float acc[4][5][4];
#pragma unroll
    for (int mi = 0; mi < 4; mi++)
#pragma unroll
        for (int ni = 0; ni < 5; ni++)
#pragma unroll
            for (int q = 0; q < 4; q++) acc[mi][ni][q] = 0.f;

    auto issueAB = [&](int c, int buf) {
        // A: 128 rows x 32 floats = 1024 cp16
#pragma unroll
        for (int it = 0; it < 2; it++) {
            int i = tid + it * 512;
            int r = i >> 3, lf = i & 7;
            int kcol = c * 32 + lf * 4;
            const float* src = X + (size_t)(row0 + r) * KACT + kcol;
            uint32_t zf = 16;
            if (KACT % 32 != 0) {
                int rem = KACT - kcol;
                if (rem >= 4) zf = 16;
                else if (rem > 0) zf = rem * 4;
                else { zf = 0; src = X; }
            }
            cp16z(sbase + buf * STAGEB + r * 144 + lf * 16, src, zf);
        }
        // B: pre-swizzled image chunk, 2880 cp16
        const char* bs = reinterpret_cast<const char*>(img) + (size_t)c * BCHB;
        uint32_t bd = sbase + buf * STAGEB + ABYTES;
        for (int i = tid; i < 2880; i += 512) cp16z(bd + i * 16, bs + i * 16, 16);
        cp_commit();
    };

    issueAB(0, 0);
    issueAB(1, 1);

    for (int c = 0; c < NC; c++) {
        const int buf = c & 1;
        if (c + 1 < NC) cp_wait1(); else cp_wait0();
        __syncthreads();

        const float* As = sm + buf * STAGEF;
        const float* Bs = sm + buf * STAGEF + AWORDS;
#pragma unroll
        for (int s = 0; s < 4; s++) {
            const int k0 = s * 8 + tg;
            uint32_t a[4][4];
#pragma unroll
            for (int mi = 0; mi < 4; mi++) {
                const float* ar = &As[(wm * 64 + mi * 16 + g) * ASTR];
                a[mi][0] = __float_as_uint(tf32r(ar[k0]));
                a[mi][1] = __float_as_uint(tf32r(ar[8 * ASTR + k0]));
                a[mi][2] = __float_as_uint(tf32r(ar[k0 + 4]));
                a[mi][3] = __float_as_uint(tf32r(ar[8 * ASTR + k0 + 4]));
            }
#pragma unroll
            for (int ni = 0; ni < 5; ni++) {
                const float* br = &Bs[(wn * 40 + ni * 8 + g) * ASTR];
                uint32_t b0 = __float_as_uint(br[k0]);
                uint32_t b1 = __float_as_uint(br[k0 + 4]);
#pragma unroll
                for (int mi = 0; mi < 4; mi++) MMA8(acc[mi][ni], a[mi], b0, b1);
            }
        }
        __syncthreads();
        if (c + 2 < NC) issueAB(c + 2, buf);
    }

    if (MODE == 0) {
#pragma unroll
        for (int mi = 0; mi < 4; mi++) {
            const int r1 = row0 + wm * 64 + mi * 16 + g, r2 = r1 + 8;
#pragma unroll
            for (int ni = 0; ni < 5; ni++) {
                const int col = wn * 40 + ni * 8 + 2 * tg;
                if (col < Dd) {
                    float2 bb = *reinterpret_cast<const float2*>(&bias[col]);
                    float2 o1 = make_float2(acc[mi][ni][0] + bb.x, acc[mi][ni][1] + bb.y);
                    float2 o2 = make_float2(acc[mi][ni][2] + bb.x, acc[mi][ni][3] + bb.y);
                    *reinterpret_cast<float2*>(&out[(size_t)r1 * Dd + col]) = o1;
                    *reinterpret_cast<float2*>(&out[(size_t)r2 * Dd + col]) = o2;
                }
            }
        }
    } else {
        float pr[8];
#pragma unroll
        for (int j = 0; j < 8; j++) pr[j] = 0.f;
#pragma unroll
        for (int mi = 0; mi < 4; mi++) {
            const int r1 = row0 + wm * 64 + mi * 16 + g, r2 = r1 + 8;
#pragma unroll
            for (int ni = 0; ni < 5; ni++) {
                const int col = wn * 40 + ni * 8 + 2 * tg;
                if (col < Dd) {
                    float2 ww = *reinterpret_cast<const float2*>(&bias[col]);
                    float2 p1 = *reinterpret_cast<const float2*>(&X[(size_t)r1 * Dd + col]);
                    float2 p2 = *reinterpret_cast<const float2*>(&X[(size_t)r2 * Dd + col]);
                    pr[mi*2+0] += (acc[mi][ni][0] + ww.x) * p1.x + (acc[mi][ni][1] + ww.y) * p1.y;
                    pr[mi*2+1] += (acc[mi][ni][2] + ww.x) * p2.x + (acc[mi][ni][3] + ww.y) * p2.y;
                }
            }
        }
#pragma unroll
        for (int j = 0; j < 8; j++) {
            pr[j] += __shfl_xor_sync(0xffffffffu, pr[j], 1);
            pr[j] += __shfl_xor_sync(0xffffffffu, pr[j], 2);
        }
        __syncthreads();
        float* red = sm;                       // [8 wn][128 rows]
        if (tg == 0) {
#pragma unroll
            for (int mi = 0; mi < 4; mi++) {
                red[wn * 128 + wm * 64 + mi * 16 + g]     = pr[mi*2+0];
                red[wn * 128 + wm * 64 + mi * 16 + g + 8] = pr[mi*2+1];
            }
        }
        __syncthreads();
        if (tid < 128) {
            float s = 0.f;
#pragma unroll
            for (int w = 0; w < 8; w++) s += red[w * 128 + tid];
            alpha[row0 + tid] = s;
        }
    }
}

// ---- prep kernels ----
__global__ void k_transpose3(const float* __restrict__ k0, const float* __restrict__ k1,
                             const float* __restrict__ k2) {
    int idx = blockIdx.x * 256 + threadIdx.x;
    if (idx >= 3 * Dd * Dd) return;
    int z = idx / (Dd * Dd), r = idx - z * (Dd * Dd);
    int j = r / Dd, d = r - j * Dd;
    const float* Wk = (z == 0) ? k0 : ((z == 1) ? k1 : k2);
    g_WkT[z * Dd * Dd + d * Dd + j] = Wk[j * Dd + d];
}

__global__ void k_wc(WPtrs p) {
    int i = blockIdx.x, z = blockIdx.y, t = threadIdx.x;
    float s = 0.f;
    if (i < Dd) {
        for (int d = t; d < Dd; d += 128)
            s += p.wq[z][i * Dd + d] * p.bk[z][d] + p.wk[z][i * Dd + d] * p.bq[z][d];
    } else {
        for (int d = t; d < Dd; d += 128) s += p.bq[z][d] * p.bk[z][d];
    }
#pragma unroll
    for (int o = 16; o > 0; o >>= 1) s += __shfl_xor_sync(0xffffffffu, s, o);
    __shared__ float smr[4];
    if ((t & 31) == 0) smr[t >> 5] = s;
    __syncthreads();
    if (t == 0) {
        float tot = smr[0] + smr[1] + smr[2] + smr[3];
        if (i < Dd) g_w[z * Dd + i] = tot; else g_c[z] = tot;
    }
}

__global__ void __launch_bounds__(320, 2)
k_gemmA(WPtrs p) {
    constexpr int TM = 32, KB = 32, K = Dd, M = Dd;
    const int z = blockIdx.y;
    const float* X = p.wq[z];
    const float* W = g_WkT + z * Dd * Dd;
    float* out = g_A + z * Dd * Dd;
    __shared__ float xs[TM][KB];
    const int tid = threadIdx.x, j = tid, row0 = blockIdx.x * TM;
    float acc[TM];
#pragma unroll
    for (int r = 0; r < TM; r++) acc[r] = 0.f;
    const int lr = tid >> 3, lk = (tid & 7) << 2;
    for (int k0 = 0; k0 < K; k0 += KB) {
        __syncthreads();
        if (tid < 256) {
            float4 v = make_float4(0.f, 0.f, 0.f, 0.f);
            int row = row0 + lr;
            if (row < M && k0 + lk < K)
                v = *reinterpret_cast<const float4*>(&X[(size_t)row * K + k0 + lk]);
            *reinterpret_cast<float4*>(&xs[lr][lk]) = v;
        }
        __syncthreads();
        if (j < Dd) {
#pragma unroll
            for (int kq = 0; kq < KB; kq += 4) {
                const float* wp = W + (size_t)(k0 + kq) * Dd + j;
                float w0 = (k0+kq+0 < K) ? wp[0] : 0.f;
                float w1 = (k0+kq+1 < K) ? wp[Dd] : 0.f;
                float w2 = (k0+kq+2 < K) ? wp[2*Dd] : 0.f;
                float w3 = (k0+kq+3 < K) ? wp[3*Dd] : 0.f;
#pragma unroll
                for (int r = 0; r < TM; r++) {
                    float4 x4 = *reinterpret_cast<const float4*>(&xs[r][kq]);
                    acc[r] = fmaf(x4.x, w0, acc[r]); acc[r] = fmaf(x4.y, w1, acc[r]);
                    acc[r] = fmaf(x4.z, w2, acc[r]); acc[r] = fmaf(x4.w, w3, acc[r]);
                }
            }
        }
    }
    if (j < Dd)
#pragma unroll
        for (int r = 0; r < TM; r++)
            if (row0 + r < M) out[(size_t)(row0 + r) * Dd + j] = acc[r];
}

// B image: [chunk][n(320) stride 36][k(32)], (k,n) = tf32r(W[k,n]), zero-padded
__global__ void k_bimg(const float* __restrict__ W, int kact, int nch, float* __restrict__ dst) {
    int i = blockIdx.x * 256 + threadIdx.x;
    if (i >= nch * NP * 32) return;
    int chunk = i / (NP * 32), r = i - chunk * (NP * 32);
    int n = r >> 5, k = r & 31;
    int kg = chunk * 32 + k;
    float v = (n < Dd && kg < kact) ? tf32r(W[(size_t)kg * Dd + n]) : 0.f;
    dst[(size_t)chunk * (NP * ASTR) + n * ASTR + k] = v;
}

__global__ void k_fac() {
    int i = blockIdx.x * 256 + threadIdx.x;
    if (i >= Bn) return;
    const float inv = 0.057735026918962576f;  // 1/sqrt(300)
    float zT = 1.f / (1.f + expf(-(g_alpha[i] + g_c[0]) * inv));
    float zI = 1.f / (1.f + expf(-(g_alpha[Bn + i] + g_c[1]) * inv));
    float zC = 1.f / (1.f + expf(-(g_alpha[2*Bn + i] + g_c[2]) * inv));
    float f = 1.f / (1.f + expf(zT * (zC - zI)));
    g_fac[i] = f;
    g_fac[Bn + i] = 1.f - f;
}

__global__ void k_scale(float4* __restrict__ o1, float4* __restrict__ o2) {
    int i = blockIdx.x * 256 + threadIdx.x;
    if (i >= Bn * 75) return;
    int r = i / 75;
    float f0 = g_fac[r], f1 = g_fac[Bn + r];
    float4 v = o1[i];
    v.x *= f0; v.y *= f0; v.z *= f0; v.w *= f0; o1[i] = v;
    float4 u = o2[i];
    u.x *= f1; u.y *= f1; u.z *= f1; u.w *= f1; o2[i] = u;
}

extern "C" void kernel_launch(void* const* d_in, const int* in_sizes, int n_in,
                              void* d_out, int out_size) {
    const float* T   = (const float*)d_in[0];
    const float* IM  = (const float*)d_in[1];
    const float* CD  = (const float*)d_in[2];
    const float* Wt  = (const float*)d_in[3];
    const float* bt  = (const float*)d_in[4];
    const float* Wim = (const float*)d_in[5];
    const float* bim = (const float*)d_in[6];
    WPtrs p;
    for (int z = 0; z < 3; z++) {
        p.wq[z] = (const float*)d_in[7 + 4*z];
        p.bq[z] = (const float*)d_in[8 + 4*z];
        p.wk[z] = (const float*)d_in[9 + 4*z];
        p.bk[z] = (const float*)d_in[10 + 4*z];
    }

    float *gA, *gw, *gAl, *gIWt, *gIWim, *gIA;
    cudaGetSymbolAddress((void**)&gA, g_A);
    cudaGetSymbolAddress((void**)&gw, g_w);
    cudaGetSymbolAddress((void**)&gAl, g_alpha);
    cudaGetSymbolAddress((void**)&gIWt, g_imgWt);
    cudaGetSymbolAddress((void**)&gIWim, g_imgWim);
    cudaGetSymbolAddress((void**)&gIA, g_imgA);

    cudaFuncSetAttribute(k_mma<Dt, 24, 0>,  cudaFuncAttributeMaxDynamicSharedMemorySize, SMEM_SZ);
    cudaFuncSetAttribute(k_mma<Dim, 64, 0>, cudaFuncAttributeMaxDynamicSharedMemorySize, SMEM_SZ);
    cudaFuncSetAttribute(k_mma<Dd, 10, 1>,  cudaFuncAttributeMaxDynamicSharedMemorySize, SMEM_SZ);

    float* out  = (float*)d_out;
    float* out0 = out;
    float* out1 = out + (size_t)Bn * Dd;
    float* out2 = out + 2 * (size_t)Bn * Dd;

    k_transpose3<<<(3*Dd*Dd + 255)/256, 256>>>(p.wk[0], p.wk[1], p.wk[2]);
    k_wc<<<dim3(Dd + 1, 3), 128>>>(p);
    k_gemmA<<<dim3((Dd + 31)/32, 3), 320>>>(p);
    k_bimg<<<(24*NP*32 + 255)/256, 256>>>(Wt,  Dt,  24, gIWt);
    k_bimg<<<(64*NP*32 + 255)/256, 256>>>(Wim, Dim, 64, gIWim);
    for (int z = 0; z < 3; z++)
        k_bimg<<<(10*NP*32 + 255)/256, 256>>>(gA + z*Dd*Dd, Dd, 10, gIA + (size_t)z*10*NP*ASTR);

    k_mma<Dt,  24, 0><<<Bn/128, 512, SMEM_SZ>>>(T,  gIWt,  bt,  out0, nullptr);
    k_mma<Dim, 64, 0><<<Bn/128, 512, SMEM_SZ>>>(IM, gIWim, bim, out1, nullptr);
    k_mma<Dt,  24, 0><<<Bn/128, 512, SMEM_SZ>>>(CD, gIWt,  bt,  out2, nullptr);

    for (int z = 0; z < 3; z++) {
        const float* src = (z == 0) ? out0 : ((z == 1) ? out1 : out2);
        k_mma<Dd, 10, 1><<<Bn/128, 512, SMEM_SZ>>>(
            src, gIA + (size_t)z*10*NP*ASTR, gw + z*Dd, nullptr, gAl + (size_t)z*Bn);
    }

    k_fac<<<(Bn + 255)/256, 256>>>();
    k_scale<<<(Bn*75 + 255)/256, 256>>>((float4*)out1, (float4*)out2);
}

// round 10
// speedup vs baseline: 4.7993x; 1.0450x over previous
#include <cuda_runtime.h>
#include <math.h>
#include <stdint.h>

#define Bn 65536
#define Dt 768
#define Dim 2048
#define Dd 300
#define NP 320
#define ASTR 36                    // A stage row stride (floats), 144B rows
#define ABYTES 18432               // 128*36*4
#define AWORDS 4608
#define BSTR 40                    // B stage row stride (floats) -> conflict-free LDS.64
#define BCHB (NP * BSTR * 4)       // 51200 B per chunk
#define BF4 (BCHB / 16)            // 3200
#define STAGEB (ABYTES + BCHB)     // 69632
#define STAGEF (STAGEB / 4)
#define SMEM_SZ (2 * STAGEB)       // 139264

__device__ float g_WkT[3 * Dd * Dd];
__device__ float g_A[3 * Dd * Dd];
__device__ float g_w[3 * Dd];
__device__ float g_c[3];
__device__ float g_alpha[3 * Bn];
__device__ float g_fac[2 * Bn];
__device__ float g_imgWt[24 * NP * BSTR];
__device__ float g_imgWim[64 * NP * BSTR];
__device__ float g_imgA[3 * 10 * NP * BSTR];

struct WPtrs { const float *wq[3], *bq[3], *wk[3], *bk[3]; };

__device__ __forceinline__ uint32_t smem_u32(const void* p) {
    uint32_t a;
    asm("{ .reg .u64 t; cvta.to.shared.u64 t, %1; cvt.u32.u64 %0, t; }" : "=r"(a) : "l"(p));
    return a;
}
__device__ __forceinline__ float tf32r(float x) {
    uint32_t r; asm("cvt.rna.tf32.f32 %0, %1;" : "=r"(r) : "f"(x));
    return __uint_as_float(r);
}
__device__ __forceinline__ void cp16z(uint32_t dst, const void* src, uint32_t zf) {
    asm volatile("cp.async.cg.shared.global [%0], [%1], 16, %2;" :: "r"(dst), "l"(src), "r"(zf));
}
__device__ __forceinline__ void cp_commit() { asm volatile("cp.async.commit_group;" ::: "memory"); }
__device__ __forceinline__ void cp_wait0() { asm volatile("cp.async.wait_group 0;" ::: "memory"); }
__device__ __forceinline__ void cp_wait1() { asm volatile("cp.async.wait_group 1;" ::: "memory"); }
__device__ __forceinline__ void ldsm4(uint32_t& r0, uint32_t& r1, uint32_t& r2, uint32_t& r3,
                                      uint32_t addr) {
    asm volatile("ldmatrix.sync.aligned.m8n8.x4.shared.b16 {%0,%1,%2,%3}, [%4];"
                 : "=r"(r0), "=r"(r1), "=r"(r2), "=r"(r3) : "r"(addr));
}

#define MMA8(d, a, b0, b1) \
    asm volatile("mma.sync.aligned.m16n8k8.row.col.f32.tf32.tf32.f32 " \
        "{%0,%1,%2,%3}, {%4,%5,%6,%7}, {%8,%9}, {%0,%1,%2,%3};" \
        : "+f"(d[0]), "+f"(d[1]), "+f"(d[2]), "+f"(d[3]) \
        : "r"(a[0]), "r"(a[1]), "r"(a[2]), "r"(a[3]), "r"(b0), "r"(b1))

// C[128x320] = X[128xK] @ W[Kx320]; MODE0: out=C+bias; MODE1: alpha=rowdot(C+w, X)
template <int KACT, int NC, int MODE>
__global__ void __launch_bounds__(512, 1)
k_mma(const float* __restrict__ X, const float* __restrict__ img,
      const float* __restrict__ bias, float* __restrict__ out, float* __restrict__ alpha) {
    extern __shared__ float sm[];
    const uint32_t sbase = smem_u32(sm);
    const int tid = threadIdx.x, lane = tid & 31, wid = tid >> 5;
    const int wm = wid & 1, wn = wid >> 1;        // 2 row-groups x 8 col-groups
    const int g = lane >> 2, tg = lane & 3;
    const int row0 = blockIdx.x * 128;

    float acc[4][5][4];
#pragma unroll
    for (int mi = 0; mi < 4; mi++)
#pragma unroll
        for (int ni = 0; ni < 5; ni++)
#pragma unroll
            for (int q = 0; q < 4; q++) acc[mi][ni][q] = 0.f;

    // ldmatrix lane base: tile = lane>>3 (0..3): tiles 0/1 rows +0/+8 at k0..3;
    // tiles 2/3 rows +0/+8 at k4..7 (+16B)
    const uint32_t lmbase =
        (uint32_t)((wm * 64 + ((lane >> 3) & 1) * 8 + (lane & 7)) * 144 + (lane >> 4) * 16);

    auto issueAB = [&](int c, int buf) {
#pragma unroll
        for (int it = 0; it < 2; it++) {
            int i = tid + it * 512;
            int r = i >> 3, lf = i & 7;
            int kcol = c * 32 + lf * 4;
            const float* src = X + (size_t)(row0 + r) * KACT + kcol;
            uint32_t zf = 16;
            if (KACT % 32 != 0) {
                int rem = KACT - kcol;
                if (rem >= 4) zf = 16;
                else if (rem > 0) zf = rem * 4;
                else { zf = 0; src = X; }
            }
            cp16z(sbase + buf * STAGEB + r * 144 + lf * 16, src, zf);
        }
        const char* bs = reinterpret_cast<const char*>(img) + (size_t)c * BCHB;
        uint32_t bd = sbase + buf * STAGEB + ABYTES;
        for (int i = tid; i < BF4; i += 512) cp16z(bd + i * 16, bs + i * 16, 16);
        cp_commit();
    };

    issueAB(0, 0);
    issueAB(1, 1);

    for (int c = 0; c < NC; c++) {
        const int buf = c & 1;
        if (c + 1 < NC) cp_wait1(); else cp_wait0();
        __syncthreads();

        const uint32_t abase = sbase + buf * STAGEB + lmbase;
        const float* Bs = sm + buf * STAGEF + AWORDS;
#pragma unroll
        for (int s = 0; s < 4; s++) {
            uint32_t a[4][4];
#pragma unroll
            for (int mi = 0; mi < 4; mi++) {
                ldsm4(a[mi][0], a[mi][1], a[mi][2], a[mi][3], abase + mi * (16 * 144) + s * 32);
#pragma unroll
                for (int q = 0; q < 4; q++)
                    a[mi][q] = __float_as_uint(tf32r(__uint_as_float(a[mi][q])));
            }
#pragma unroll
            for (int ni = 0; ni < 5; ni++) {
                // pair-permuted: (k0=tg, k0+4) stored contiguously at s*8 + 2*tg
                float2 bp = *reinterpret_cast<const float2*>(
                    &Bs[(wn * 40 + ni * 8 + g) * BSTR + s * 8 + 2 * tg]);
                uint32_t b0 = __float_as_uint(bp.x);
                uint32_t b1 = __float_as_uint(bp.y);
#pragma unroll
                for (int mi = 0; mi < 4; mi++) MMA8(acc[mi][ni], a[mi], b0, b1);
            }
        }
        __syncthreads();
        if (c + 2 < NC) issueAB(c + 2, buf);
    }

    if (MODE == 0) {
#pragma unroll
        for (int mi = 0; mi < 4; mi++) {
            const int r1 = row0 + wm * 64 + mi * 16 + g, r2 = r1 + 8;
#pragma unroll
            for (int ni = 0; ni < 5; ni++) {
                const int col = wn * 40 + ni * 8 + 2 * tg;
                if (col < Dd) {
                    float2 bb = *reinterpret_cast<const float2*>(&bias[col]);
                    float2 o1 = make_float2(acc[mi][ni][0] + bb.x, acc[mi][ni][1] + bb.y);
                    float2 o2 = make_float2(acc[mi][ni][2] + bb.x, acc[mi][ni][3] + bb.y);
                    *reinterpret_cast<float2*>(&out[(size_t)r1 * Dd + col]) = o1;
                    *reinterpret_cast<float2*>(&out[(size_t)r2 * Dd + col]) = o2;
                }
            }
        }
    } else {
        float pr[8];
#pragma unroll
        for (int j = 0; j < 8; j++) pr[j] = 0.f;
#pragma unroll
        for (int mi = 0; mi < 4; mi++) {
            const int r1 = row0 + wm * 64 + mi * 16 + g, r2 = r1 + 8;
#pragma unroll
            for (int ni = 0; ni < 5; ni++) {
                const int col = wn * 40 + ni * 8 + 2 * tg;
                if (col < Dd) {
                    float2 ww = *reinterpret_cast<const float2*>(&bias[col]);
                    float2 p1 = *reinterpret_cast<const float2*>(&X[(size_t)r1 * Dd + col]);
                    float2 p2 = *reinterpret_cast<const float2*>(&X[(size_t)r2 * Dd + col]);
                    pr[mi*2+0] += (acc[mi][ni][0] + ww.x) * p1.x + (acc[mi][ni][1] + ww.y) * p1.y;
                    pr[mi*2+1] += (acc[mi][ni][2] + ww.x) * p2.x + (acc[mi][ni][3] + ww.y) * p2.y;
                }
            }
        }
#pragma unroll
        for (int j = 0; j < 8; j++) {
            pr[j] += __shfl_xor_sync(0xffffffffu, pr[j], 1);
            pr[j] += __shfl_xor_sync(0xffffffffu, pr[j], 2);
        }
        __syncthreads();
        float* red = sm;                       // [8 wn][128 rows]
        if (tg == 0) {
#pragma unroll
            for (int mi = 0; mi < 4; mi++) {
                red[wn * 128 + wm * 64 + mi * 16 + g]     = pr[mi*2+0];
                red[wn * 128 + wm * 64 + mi * 16 + g + 8] = pr[mi*2+1];
            }
        }
        __syncthreads();
        if (tid < 128) {
            float s = 0.f;
#pragma unroll
            for (int w = 0; w < 8; w++) s += red[w * 128 + tid];
            alpha[row0 + tid] = s;
        }
    }
}

// ---- prep kernels ----
__global__ void k_transpose3(const float* __restrict__ k0, const float* __restrict__ k1,
                             const float* __restrict__ k2) {
    int idx = blockIdx.x * 256 + threadIdx.x;
    if (idx >= 3 * Dd * Dd) return;
    int z = idx / (Dd * Dd), r = idx - z * (Dd * Dd);
    int j = r / Dd, d = r - j * Dd;
    const float* Wk = (z == 0) ? k0 : ((z == 1) ? k1 : k2);
    g_WkT[z * Dd * Dd + d * Dd + j] = Wk[j * Dd + d];
}

__global__ void k_wc(WPtrs p) {
    int i = blockIdx.x, z = blockIdx.y, t = threadIdx.x;
    float s = 0.f;
    if (i < Dd) {
        for (int d = t; d < Dd; d += 128)
            s += p.wq[z][i * Dd + d] * p.bk[z][d] + p.wk[z][i * Dd + d] * p.bq[z][d];
    } else {
        for (int d = t; d < Dd; d += 128) s += p.bq[z][d] * p.bk[z][d];
    }
#pragma unroll
    for (int o = 16; o > 0; o >>= 1) s += __shfl_xor_sync(0xffffffffu, s, o);
    __shared__ float smr[4];
    if ((t & 31) == 0) smr[t >> 5] = s;
    __syncthreads();
    if (t == 0) {
        float tot = smr[0] + smr[1] + smr[2] + smr[3];
        if (i < Dd) g_w[z * Dd + i] = tot; else g_c[z] = tot;
    }
}

__global__ void __launch_bounds__(320, 2)
k_gemmA(WPtrs p) {
    constexpr int TM = 32, KB = 32, K = Dd, M = Dd;
    const int z = blockIdx.y;
    const float* X = p.wq[z];
    const float* W = g_WkT + z * Dd * Dd;
    float* out = g_A + z * Dd * Dd;
    __shared__ float xs[TM][KB];
    const int tid = threadIdx.x, j = tid, row0 = blockIdx.x * TM;
    float acc[TM];
#pragma unroll
    for (int r = 0; r < TM; r++) acc[r] = 0.f;
    const int lr = tid >> 3, lk = (tid & 7) << 2;
    for (int k0 = 0; k0 < K; k0 += KB) {
        __syncthreads();
        if (tid < 256) {
            float4 v = make_float4(0.f, 0.f, 0.f, 0.f);
            int row = row0 + lr;
            if (row < M && k0 + lk < K)
                v = *reinterpret_cast<const float4*>(&X[(size_t)row * K + k0 + lk]);
            *reinterpret_cast<float4*>(&xs[lr][lk]) = v;
        }
        __syncthreads();
        if (j < Dd) {
#pragma unroll
            for (int kq = 0; kq < KB; kq += 4) {
                const float* wp = W + (size_t)(k0 + kq) * Dd + j;
                float w0 = (k0+kq+0 < K) ? wp[0] : 0.f;
                float w1 = (k0+kq+1 < K) ? wp[Dd] : 0.f;
                float w2 = (k0+kq+2 < K) ? wp[2*Dd] : 0.f;
                float w3 = (k0+kq+3 < K) ? wp[3*Dd] : 0.f;
#pragma unroll
                for (int r = 0; r < TM; r++) {
                    float4 x4 = *reinterpret_cast<const float4*>(&xs[r][kq]);
                    acc[r] = fmaf(x4.x, w0, acc[r]); acc[r] = fmaf(x4.y, w1, acc[r]);
                    acc[r] = fmaf(x4.z, w2, acc[r]); acc[r] = fmaf(x4.w, w3, acc[r]);
                }
            }
        }
    }
    if (j < Dd)
#pragma unroll
        for (int r = 0; r < TM; r++)
            if (row0 + r < M) out[(size_t)(row0 + r) * Dd + j] = acc[r];
}

// B image: [chunk][n(320) stride 40][k permuted per 8-group: k0,k4,k1,k5,k2,k6,k3,k7]
__global__ void k_bimg(const float* __restrict__ W, int kact, int nch, float* __restrict__ dst) {
    int i = blockIdx.x * 256 + threadIdx.x;
    if (i >= nch * NP * 32) return;
    int chunk = i / (NP * 32), r = i - chunk * (NP * 32);
    int n = r >> 5, k = r & 31;
    int kg = chunk * 32 + k;
    float v = (n < Dd && kg < kact) ? tf32r(W[(size_t)kg * Dd + n]) : 0.f;
    int s = k >> 3, j = k & 7;
    int pos = s * 8 + ((j < 4) ? (2 * j) : (2 * (j - 4) + 1));
    dst[(size_t)chunk * (NP * BSTR) + n * BSTR + pos] = v;
}

__global__ void k_fac() {
    int i = blockIdx.x * 256 + threadIdx.x;
    if (i >= Bn) return;
    const float inv = 0.057735026918962576f;  // 1/sqrt(300)
    float zT = 1.f / (1.f + expf(-(g_alpha[i] + g_c[0]) * inv));
    float zI = 1.f / (1.f + expf(-(g_alpha[Bn + i] + g_c[1]) * inv));
    float zC = 1.f / (1.f + expf(-(g_alpha[2*Bn + i] + g_c[2]) * inv));
    float f = 1.f / (1.f + expf(zT * (zC - zI)));
    g_fac[i] = f;
    g_fac[Bn + i] = 1.f - f;
}

__global__ void k_scale(float4* __restrict__ o1, float4* __restrict__ o2) {
    int i = blockIdx.x * 256 + threadIdx.x;
    if (i >= Bn * 75) return;
    int r = i / 75;
    float f0 = g_fac[r], f1 = g_fac[Bn + r];
    float4 v = o1[i];
    v.x *= f0; v.y *= f0; v.z *= f0; v.w *= f0; o1[i] = v;
    float4 u = o2[i];
    u.x *= f1; u.y *= f1; u.z *= f1; u.w *= f1; o2[i] = u;
}

extern "C" void kernel_launch(void* const* d_in, const int* in_sizes, int n_in,
                              void* d_out, int out_size) {
    const float* T   = (const float*)d_in[0];
    const float* IM  = (const float*)d_in[1];
    const float* CD  = (const float*)d_in[2];
    const float* Wt  = (const float*)d_in[3];
    const float* bt  = (const float*)d_in[4];
    const float* Wim = (const float*)d_in[5];
    const float* bim = (const float*)d_in[6];
    WPtrs p;
    for (int z = 0; z < 3; z++) {
        p.wq[z] = (const float*)d_in[7 + 4*z];
        p.bq[z] = (const float*)d_in[8 + 4*z];
        p.wk[z] = (const float*)d_in[9 + 4*z];
        p.bk[z] = (const float*)d_in[10 + 4*z];
    }

    float *gA, *gw, *gAl, *gIWt, *gIWim, *gIA;
    cudaGetSymbolAddress((void**)&gA, g_A);
    cudaGetSymbolAddress((void**)&gw, g_w);
    cudaGetSymbolAddress((void**)&gAl, g_alpha);
    cudaGetSymbolAddress((void**)&gIWt, g_imgWt);
    cudaGetSymbolAddress((void**)&gIWim, g_imgWim);
    cudaGetSymbolAddress((void**)&gIA, g_imgA);

    cudaFuncSetAttribute(k_mma<Dt, 24, 0>,  cudaFuncAttributeMaxDynamicSharedMemorySize, SMEM_SZ);
    cudaFuncSetAttribute(k_mma<Dim, 64, 0>, cudaFuncAttributeMaxDynamicSharedMemorySize, SMEM_SZ);
    cudaFuncSetAttribute(k_mma<Dd, 10, 1>,  cudaFuncAttributeMaxDynamicSharedMemorySize, SMEM_SZ);

    float* out  = (float*)d_out;
    float* out0 = out;
    float* out1 = out + (size_t)Bn * Dd;
    float* out2 = out + 2 * (size_t)Bn * Dd;

    // prep needed for the projections (launches 1-5); k_mma<Dt>(T) is launch 6,
    // which is what ncu's "-s 5 -c 1" captures -> real GEMM profile next round.
    k_transpose3<<<(3*Dd*Dd + 255)/256, 256>>>(p.wk[0], p.wk[1], p.wk[2]);
    k_wc<<<dim3(Dd + 1, 3), 128>>>(p);
    k_gemmA<<<dim3((Dd + 31)/32, 3), 320>>>(p);
    k_bimg<<<(24*NP*32 + 255)/256, 256>>>(Wt,  Dt,  24, gIWt);
    k_bimg<<<(64*NP*32 + 255)/256, 256>>>(Wim, Dim, 64, gIWim);

    k_mma<Dt,  24, 0><<<Bn/128, 512, SMEM_SZ>>>(T,  gIWt,  bt,  out0, nullptr);   // launch 6
    k_mma<Dim, 64, 0><<<Bn/128, 512, SMEM_SZ>>>(IM, gIWim, bim, out1, nullptr);
    k_mma<Dt,  24, 0><<<Bn/128, 512, SMEM_SZ>>>(CD, gIWt,  bt,  out2, nullptr);

    // A_z images depend only on k_gemmA (done); stream order keeps them after projections
    for (int z = 0; z < 3; z++)
        k_bimg<<<(10*NP*32 + 255)/256, 256>>>(gA + z*Dd*Dd, Dd, 10, gIA + (size_t)z*10*NP*BSTR);

    for (int z = 0; z < 3; z++) {
        const float* src = (z == 0) ? out0 : ((z == 1) ? out1 : out2);
        k_mma<Dd, 10, 1><<<Bn/128, 512, SMEM_SZ>>>(
            src, gIA + (size_t)z*10*NP*BSTR, gw + z*Dd, nullptr, gAl + (size_t)z*Bn);
    }

    k_fac<<<(Bn + 255)/256, 256>>>();
    k_scale<<<(Bn*75 + 255)/256, 256>>>((float4*)out1, (float4*)out2);
}